// round 1
// baseline (speedup 1.0000x reference)
#include <cuda_runtime.h>

#define L 2048
#define B 32
#define H 1024
#define GCH 8            // g-chunks for K1 partials
#define GSZ (H / GCH)    // 128
#define LTILES 16
#define LPT (L / LTILES) // 128 l-positions per K2 block

// Scratch (allocation-free rule: __device__ globals)
__device__ float g_vpart[GCH][B][H];   // 1 MB partial v
__device__ float g_energy[B][L];       // 256 KB energies

// ---------------------------------------------------------------------------
// K1: v_part[gc][b][h] = sum_{g in chunk gc} hidden[b,g] * W[g,h]
// grid (H/128, B/8, GCH), block (32, 8). Each thread: 4 h-cols, 1 b, 128 g.
// ---------------------------------------------------------------------------
__global__ void k1_proj(const float* __restrict__ hidden,
                        const float* __restrict__ W) {
    const int tx = threadIdx.x, ty = threadIdx.y;
    const int h0 = blockIdx.x * 128;
    const int b0 = blockIdx.y * 8;
    const int g0 = blockIdx.z * GSZ;

    __shared__ float hsh[GSZ][8];   // hidden chunk, transposed [g][b_local]
    const int tid = ty * 32 + tx;
    for (int i = tid; i < 8 * GSZ; i += 256) {
        const int bl = i / GSZ, g = i % GSZ;
        hsh[g][bl] = hidden[(size_t)(b0 + bl) * H + g0 + g];
    }
    __syncthreads();

    const float4* __restrict__ W4 = (const float4*)W;
    const int hcol = h0 + tx * 4;
    float4 acc = make_float4(0.f, 0.f, 0.f, 0.f);
    #pragma unroll 4
    for (int g = 0; g < GSZ; g++) {
        const float4 w = W4[((size_t)(g0 + g) * H + hcol) >> 2];
        const float hb = hsh[g][ty];
        acc.x += w.x * hb; acc.y += w.y * hb;
        acc.z += w.z * hb; acc.w += w.w * hb;
    }
    *(float4*)&g_vpart[blockIdx.z][b0 + ty][hcol] = acc;
}

// ---------------------------------------------------------------------------
// K2: energies[b][l] = dot(enc[l,b,:], v[b,:])
// grid (LTILES, B), block 256 (8 warps, 16 l's per warp).
// v reduced from partials into 4 KB smem once per block.
// ---------------------------------------------------------------------------
__global__ void k2_energy(const float* __restrict__ enc) {
    const int b  = blockIdx.y;
    const int l0 = blockIdx.x * LPT;
    const int tid = threadIdx.x;

    __shared__ float4 vsh[H / 4];   // 4 KB
    {
        float4 s = make_float4(0.f, 0.f, 0.f, 0.f);
        #pragma unroll
        for (int p = 0; p < GCH; p++) {
            const float4 v = *(const float4*)&g_vpart[p][b][tid * 4];
            s.x += v.x; s.y += v.y; s.z += v.z; s.w += v.w;
        }
        vsh[tid] = s;
    }
    __syncthreads();

    const int warp = tid >> 5, lane = tid & 31;
    const float4* __restrict__ enc4 = (const float4*)enc;

    #pragma unroll 2
    for (int i = 0; i < 16; i++) {
        const int l = l0 + warp * 16 + i;
        const size_t base = ((size_t)l * B + b) * (H / 4);
        float acc = 0.f;
        #pragma unroll
        for (int k = 0; k < 8; k++) {
            const float4 e = enc4[base + k * 32 + lane];
            const float4 v = vsh[k * 32 + lane];
            acc += e.x * v.x + e.y * v.y + e.z * v.z + e.w * v.w;
        }
        #pragma unroll
        for (int s = 16; s; s >>= 1)
            acc += __shfl_down_sync(0xffffffffu, acc, s);
        if (lane == 0) g_energy[b][l] = acc;
    }
}

// ---------------------------------------------------------------------------
// K3: masked softmax per batch row. grid B, block 256, 8 l's per thread.
// out[b,0,l] = valid ? exp(e - max)/sum : 0
// ---------------------------------------------------------------------------
__global__ void k3_softmax(const int* __restrict__ lengths,
                           float* __restrict__ out) {
    const int b   = blockIdx.x;
    const int len = lengths[b];
    const int tid = threadIdx.x;

    float e[8];
    float mx = -3.4e38f;
    #pragma unroll
    for (int i = 0; i < 8; i++) {
        const int l = tid + i * 256;
        e[i] = g_energy[b][l];
        if (l < len) mx = fmaxf(mx, e[i]);
    }

    __shared__ float red[8];
    #pragma unroll
    for (int s = 16; s; s >>= 1)
        mx = fmaxf(mx, __shfl_xor_sync(0xffffffffu, mx, s));
    if ((tid & 31) == 0) red[tid >> 5] = mx;
    __syncthreads();
    mx = red[0];
    #pragma unroll
    for (int w = 1; w < 8; w++) mx = fmaxf(mx, red[w]);
    __syncthreads();   // protect red[] before reuse

    float ex[8];
    float sum = 0.f;
    #pragma unroll
    for (int i = 0; i < 8; i++) {
        const int l = tid + i * 256;
        ex[i] = (l < len) ? expf(e[i] - mx) : 0.f;
        sum += ex[i];
    }
    #pragma unroll
    for (int s = 16; s; s >>= 1)
        sum += __shfl_xor_sync(0xffffffffu, sum, s);
    if ((tid & 31) == 0) red[tid >> 5] = sum;
    __syncthreads();
    float total = 0.f;
    #pragma unroll
    for (int w = 0; w < 8; w++) total += red[w];
    const float inv = 1.f / total;

    #pragma unroll
    for (int i = 0; i < 8; i++) {
        const int l = tid + i * 256;
        out[(size_t)b * L + l] = ex[i] * inv;
    }
}

// ---------------------------------------------------------------------------
extern "C" void kernel_launch(void* const* d_in, const int* in_sizes, int n_in,
                              void* d_out, int out_size) {
    const float* hidden  = (const float*)d_in[0];   // [1,B,H]
    const float* enc     = (const float*)d_in[1];   // [L,B,H]
    const float* W       = (const float*)d_in[2];   // [H,H]
    // d_in[3] = bias — provably cancels in softmax, unused
    const int*   lengths = (const int*)d_in[4];     // [B]
    float* out = (float*)d_out;                     // [B,1,L]

    dim3 g1(H / 128, B / 8, GCH), b1(32, 8);
    k1_proj<<<g1, b1>>>(hidden, W);

    dim3 g2(LTILES, B);
    k2_energy<<<g2, 256>>>(enc);

    k3_softmax<<<B, 256>>>(lengths, out);
}